// round 15
// baseline (speedup 1.0000x reference)
#include <cuda_runtime.h>
#include <cuda_bf16.h>

#define B_    4
#define N_    512
#define INF_  256
#define OUTF  128
#define HALFF 64
#define EDGEF 16

// ---------------- scratch ----------------
__device__ float g_Wh[B_ * N_ * OUTF];
__device__ float g_f1[B_ * N_];
__device__ float g_f2[B_ * N_];
__device__ float g_att[B_ * N_ * N_];
__device__ float g_dummy[32];

// ---------------- helpers ----------------
__device__ __forceinline__ unsigned f2bf(float v) {
    return (unsigned)__bfloat16_as_ushort(__float2bfloat16_rn(v));
}
__device__ __forceinline__ float bfu2f(unsigned u) {
    return __bfloat162float(__ushort_as_bfloat16((unsigned short)u));
}
// packed bf16x2 convert: d.hi = bf16(hi), d.lo = bf16(lo), round-to-nearest
__device__ __forceinline__ unsigned cvt2(float hi, float lo) {
    unsigned r;
    asm("cvt.rn.bf16x2.f32 %0, %1, %2;" : "=r"(r) : "f"(hi), "f"(lo));
    return r;
}
// pack bf16(x),bf16(y) into h (x->low), residuals into l — bit-identical
// to the scalar split2 path, 6 ops instead of 8.
__device__ __forceinline__ void splitpack(float x, float y, unsigned& h, unsigned& l) {
    h = cvt2(y, x);
    float hx = __uint_as_float(h << 16);
    float hy = __uint_as_float(h & 0xffff0000u);
    l = cvt2(y - hy, x - hx);
}

__device__ __forceinline__ void mma16816(float* c, const unsigned* a, const unsigned* b) {
    asm volatile(
        "mma.sync.aligned.m16n8k16.row.col.f32.bf16.bf16.f32 "
        "{%0,%1,%2,%3}, {%4,%5,%6,%7}, {%8,%9}, {%0,%1,%2,%3};"
        : "+f"(c[0]), "+f"(c[1]), "+f"(c[2]), "+f"(c[3])
        : "r"(a[0]), "r"(a[1]), "r"(a[2]), "r"(a[3]), "r"(b[0]), "r"(b[1]));
}

// =================================================================
// Kernel D: dummy. Pattern A,D,D,B,C,D keeps kernB at cycle pos 3
// (captured index k ≡ 3 mod 6) so ncu keeps profiling kernB.
// =================================================================
__global__ void kernD() {
    if (threadIdx.x < 32) g_dummy[threadIdx.x] = (float)threadIdx.x;
}

// =================================================================
// Kernel A: Wh = h @ W, f1 = Wh@a[:128], f2 = Wh@a[128:]
// grid (128, 4) x 256 threads; 4 rows per CTA, K split across 2 halves.
// =================================================================
__global__ void __launch_bounds__(256) kernA(
    const float* __restrict__ h, const float* __restrict__ W,
    const float* __restrict__ a)
{
    int b = blockIdx.y, i0 = blockIdx.x * 4;
    int tid = threadIdx.x, d = tid & 127, kh = tid >> 7;
    __shared__ float h_s[4 * 256];
    __shared__ float a_s[256];
    __shared__ float part[4][128];
    __shared__ float red[2][8];

    a_s[tid] = a[tid];
    {
        const float4* hg = (const float4*)(h + ((long)b * N_ + i0) * INF_);
        ((float4*)h_s)[tid] = hg[tid];
    }
    __syncthreads();

    float acc[4] = {0.f, 0.f, 0.f, 0.f};
    const float* Wp = W + d;
    int k0 = kh * 128;
#pragma unroll 16
    for (int k = 0; k < 128; k++) {
        float w = Wp[(k0 + k) * OUTF];
#pragma unroll
        for (int r = 0; r < 4; r++) acc[r] += h_s[r * 256 + k0 + k] * w;
    }

    if (kh) {
#pragma unroll
        for (int r = 0; r < 4; r++) part[r][d] = acc[r];
    }
    __syncthreads();

    float tot[4];
#pragma unroll
    for (int r = 0; r < 4; r++)
        tot[r] = kh ? 0.f : (acc[r] + part[r][d]);

    int lane = tid & 31, wrp = tid >> 5;
    for (int r = 0; r < 4; r++) {
        int row = b * N_ + i0 + r;
        if (!kh) g_Wh[row * OUTF + d] = tot[r];
        float v1 = tot[r] * a_s[d];
        float v2 = tot[r] * a_s[128 + d];
#pragma unroll
        for (int o = 16; o; o >>= 1) {
            v1 += __shfl_down_sync(~0u, v1, o);
            v2 += __shfl_down_sync(~0u, v2, o);
        }
        if (lane == 0) { red[0][wrp] = v1; red[1][wrp] = v2; }
        __syncthreads();
        if (tid == 0) {
            float t1 = 0.f, t2 = 0.f;
            for (int k = 0; k < 8; k++) { t1 += red[0][k]; t2 += red[1][k]; }
            g_f1[row] = t1; g_f2[row] = t2;
        }
        __syncthreads();
    }
}

// =================================================================
// Kernel B: edge FFN, bf16 3-term mma. R9 structure (16-row warps,
// minblocks 3 — best measured). NEW: B-fragment pairs stored as uint2
// so each fragment is one LDS.64 (issue-slot diet; crossbar-neutral),
// and packed bf16x2 converts. Math bit-identical to the 264us best.
// One CTA (8 warps) per (b,i); 4 j-tiles of 128.
// =================================================================
#define W1P 5    // uint2 pitch: 4 pairs + 1 pad
#define W2P 33   // uint2 pitch: 32 pairs + 1 pad

__global__ void __launch_bounds__(256, 3) kernB(
    const float* __restrict__ edge,
    const float* __restrict__ w1g, const float* __restrict__ b1g,
    const float* __restrict__ w2g, const float* __restrict__ b2g,
    float* __restrict__ out1)
{
    __shared__ uint2 w1p[128 * W1P], w1q[128 * W1P];   // hi, lo
    __shared__ uint2 w2p[64 * W2P],  w2q[64 * W2P];    // hi, lo
    __shared__ float b1s[128], b2s[64];

    int tid = threadIdx.x, wid = tid >> 5, lane = tid & 31;
    int g = lane >> 2, c = lane & 3;
    int b = blockIdx.y, i = blockIdx.x;

    // stage w1: fragment pair (kp=c, kp=c+4) adjacent in one uint2
    for (int idx = tid; idx < 512; idx += 256) {
        int n = idx >> 2, cc = idx & 3;
        unsigned h1, l1, h2, l2;
        splitpack(w1g[(2 * cc)     * OUTF + n], w1g[(2 * cc + 1) * OUTF + n], h1, l1);
        splitpack(w1g[(2 * cc + 8) * OUTF + n], w1g[(2 * cc + 9) * OUTF + n], h2, l2);
        w1p[n * W1P + cc] = make_uint2(h1, h2);
        w1q[n * W1P + cc] = make_uint2(l1, l2);
    }
    // stage w2: fragment pair (kp=8s+c, kp=8s+c+4) adjacent
    for (int idx = tid; idx < 2048; idx += 256) {
        int n = idx >> 5, r = idx & 31, s = r >> 2, cc = r & 3;
        int kp1 = 8 * s + cc, kp2 = kp1 + 4;
        unsigned h1, l1, h2, l2;
        splitpack(w2g[(2 * kp1) * HALFF + n], w2g[(2 * kp1 + 1) * HALFF + n], h1, l1);
        splitpack(w2g[(2 * kp2) * HALFF + n], w2g[(2 * kp2 + 1) * HALFF + n], h2, l2);
        w2p[n * W2P + s * 4 + cc] = make_uint2(h1, h2);
        w2q[n * W2P + s * 4 + cc] = make_uint2(l1, l2);
    }
    if (tid < 128)      b1s[tid]       = b1g[tid];
    else if (tid < 192) b2s[tid - 128] = b2g[tid - 128];
    __syncthreads();

    float f1v = g_f1[b * N_ + i];
    long erow = ((long)(b * N_ + i)) * N_;

    for (int t = 0; t < 4; t++) {
        int jt = t * 128 + wid * 16;
        const float* ep = edge + (erow + jt) * EDGEF;

        // edge A fragments straight from gmem, hi/lo split
        unsigned ah[4], al[4];
        {
            float2 v0 = *(const float2*)(ep + (g)     * EDGEF + 2 * c);
            float2 v1 = *(const float2*)(ep + (g + 8) * EDGEF + 2 * c);
            float2 v2 = *(const float2*)(ep + (g)     * EDGEF + 2 * c + 8);
            float2 v3 = *(const float2*)(ep + (g + 8) * EDGEF + 2 * c + 8);
            splitpack(v0.x, v0.y, ah[0], al[0]);
            splitpack(v1.x, v1.y, ah[1], al[1]);
            splitpack(v2.x, v2.y, ah[2], al[2]);
            splitpack(v3.x, v3.y, ah[3], al[3]);
        }

        float c2[8][4];
#pragma unroll
        for (int nt = 0; nt < 8; nt++)
            c2[nt][0] = c2[nt][1] = c2[nt][2] = c2[nt][3] = 0.f;

        // fused: per K-chunk s, build EH cols [16s,16s+16) then consume them
#pragma unroll
        for (int s = 0; s < 8; s++) {
            unsigned Ah[4], Al[4];
#pragma unroll
            for (int q = 0; q < 2; q++) {
                int nt1 = 2 * s + q;
                int n = nt1 * 8 + g;
                uint2 fh = w1p[n * W1P + c];
                uint2 fl = w1q[n * W1P + c];
                unsigned bh[2] = { fh.x, fh.y }, bl[2] = { fl.x, fl.y };
                float c1[4] = {0.f, 0.f, 0.f, 0.f};
                mma16816(c1, ah, bh);
                mma16816(c1, ah, bl);
                mma16816(c1, al, bh);
                float bx = b1s[nt1 * 8 + 2 * c], by = b1s[nt1 * 8 + 2 * c + 1];
                float r0 = fmaxf(c1[0] + bx, 0.f);
                float r1 = fmaxf(c1[1] + by, 0.f);
                float r2 = fmaxf(c1[2] + bx, 0.f);
                float r3 = fmaxf(c1[3] + by, 0.f);
                splitpack(r0, r1, Ah[2 * q],     Al[2 * q]);
                splitpack(r2, r3, Ah[2 * q + 1], Al[2 * q + 1]);
            }
#pragma unroll
            for (int nt = 0; nt < 8; nt++) {
                int n = nt * 8 + g;
                uint2 gh = w2p[n * W2P + s * 4 + c];
                uint2 gl = w2q[n * W2P + s * 4 + c];
                unsigned bh[2] = { gh.x, gh.y }, bl[2] = { gl.x, gl.y };
                mma16816(c2[nt], Ah, bh);
                mma16816(c2[nt], Ah, bl);
                mma16816(c2[nt], Al, bh);
            }
        }

        // epilogue: bias + relu, write out1, fold row sums into att logits
        float sum_g = 0.f, sum_g8 = 0.f;
        float* op = out1 + (erow + jt) * HALFF;
#pragma unroll
        for (int nt = 0; nt < 8; nt++) {
            float bx = b2s[nt * 8 + 2 * c], by = b2s[nt * 8 + 2 * c + 1];
            float r0 = fmaxf(c2[nt][0] + bx, 0.f);
            float r1 = fmaxf(c2[nt][1] + by, 0.f);
            float r2 = fmaxf(c2[nt][2] + bx, 0.f);
            float r3 = fmaxf(c2[nt][3] + by, 0.f);
            sum_g  += r0 + r1;
            sum_g8 += r2 + r3;
            *(float2*)(op + (long)(g)     * HALFF + nt * 8 + 2 * c) = make_float2(r0, r1);
            *(float2*)(op + (long)(g + 8) * HALFF + nt * 8 + 2 * c) = make_float2(r2, r3);
        }
        sum_g  += __shfl_xor_sync(~0u, sum_g, 1);
        sum_g  += __shfl_xor_sync(~0u, sum_g, 2);
        sum_g8 += __shfl_xor_sync(~0u, sum_g8, 1);
        sum_g8 += __shfl_xor_sync(~0u, sum_g8, 2);
        if (c == 0) {
            int j = jt + g;
            float e = f1v + g_f2[b * N_ + j];
            e = e > 0.f ? e : 0.2f * e;
            g_att[erow + j] = e * (64.f + sum_g);
            j += 8;
            float e2 = f1v + g_f2[b * N_ + j];
            e2 = e2 > 0.f ? e2 : 0.2f * e2;
            g_att[erow + j] = e2 * (64.f + sum_g8);
        }
    }
}

// =================================================================
// Kernel C: normalize / mask / softmax / h' = att@Wh + x / elu
// 8 rows per CTA; reductions batched. grid (64, 4) x 256 threads.
// =================================================================
__global__ void __launch_bounds__(256) kernC(
    const int* __restrict__ adj, const float* __restrict__ x,
    float* __restrict__ out0)
{
    int b = blockIdx.y, i0 = blockIdx.x * 8;
    int tid = threadIdx.x, lane = tid & 31, wrp = tid >> 5;

    __shared__ float att_s[8][512];
    __shared__ float red[8][8];
    __shared__ float bc[8];
    __shared__ float inv8[8];
    __shared__ float part[8][128];

    float v0[8], v1[8];
    int m0[8], m1[8];
#pragma unroll
    for (int r = 0; r < 8; r++) {
        int row = b * N_ + i0 + r;
        const float* ar   = g_att + (long)row * N_;
        const int*   adjr = adj   + (long)row * N_;
        v0[r] = ar[tid]; v1[r] = ar[tid + 256];
        m0[r] = adjr[tid]; m1[r] = adjr[tid + 256];
    }

    float mx[8];
#pragma unroll
    for (int r = 0; r < 8; r++) mx[r] = fmaxf(v0[r], v1[r]);
#pragma unroll
    for (int o = 16; o; o >>= 1)
#pragma unroll
        for (int r = 0; r < 8; r++)
            mx[r] = fmaxf(mx[r], __shfl_down_sync(~0u, mx[r], o));
    if (lane == 0)
#pragma unroll
        for (int r = 0; r < 8; r++) red[r][wrp] = mx[r];
    __syncthreads();
    if (tid < 8) {
        float t = red[tid][0];
        for (int k = 1; k < 8; k++) t = fmaxf(t, red[tid][k]);
        bc[tid] = t;
    }
    __syncthreads();

    float a0[8], a1[8];
#pragma unroll
    for (int r = 0; r < 8; r++) {
        float scale = 1.f / (fabsf(bc[r]) + 1e-6f);
        a0[r] = m0[r] > 0 ? v0[r] * scale : -1e6f;
        a1[r] = m1[r] > 0 ? v1[r] * scale : -1e6f;
    }
    __syncthreads();

#pragma unroll
    for (int r = 0; r < 8; r++) mx[r] = fmaxf(a0[r], a1[r]);
#pragma unroll
    for (int o = 16; o; o >>= 1)
#pragma unroll
        for (int r = 0; r < 8; r++)
            mx[r] = fmaxf(mx[r], __shfl_down_sync(~0u, mx[r], o));
    if (lane == 0)
#pragma unroll
        for (int r = 0; r < 8; r++) red[r][wrp] = mx[r];
    __syncthreads();
    if (tid < 8) {
        float t = red[tid][0];
        for (int k = 1; k < 8; k++) t = fmaxf(t, red[tid][k]);
        bc[tid] = t;
    }
    __syncthreads();

    float sm[8];
#pragma unroll
    for (int r = 0; r < 8; r++) {
        float p0 = expf(a0[r] - bc[r]), p1 = expf(a1[r] - bc[r]);
        att_s[r][tid] = p0; att_s[r][tid + 256] = p1;
        sm[r] = p0 + p1;
    }
#pragma unroll
    for (int o = 16; o; o >>= 1)
#pragma unroll
        for (int r = 0; r < 8; r++)
            sm[r] += __shfl_down_sync(~0u, sm[r], o);
    __syncthreads();
    if (lane == 0)
#pragma unroll
        for (int r = 0; r < 8; r++) red[r][wrp] = sm[r];
    __syncthreads();
    if (tid < 8) {
        float t = 0.f;
        for (int k = 0; k < 8; k++) t += red[tid][k];
        inv8[tid] = 1.f / t;
    }
    __syncthreads();

    int d = tid & 127, half = tid >> 7;
    const float* wh = g_Wh + (long)(b * N_ + half * 256) * OUTF + d;
    float acc[8];
#pragma unroll
    for (int r = 0; r < 8; r++) acc[r] = 0.f;
#pragma unroll 8
    for (int j = 0; j < 256; j++) {
        float wv = wh[j * OUTF];
        int jj = half * 256 + j;
#pragma unroll
        for (int r = 0; r < 8; r++) acc[r] += att_s[r][jj] * wv;
    }
    if (half) {
#pragma unroll
        for (int r = 0; r < 8; r++) part[r][d] = acc[r];
    }
    __syncthreads();
    if (!half) {
#pragma unroll
        for (int r = 0; r < 8; r++) {
            int row = b * N_ + i0 + r;
            float hp = (acc[r] + part[r][d]) * inv8[r] + x[(long)row * OUTF + d];
            out0[(long)row * OUTF + d] = hp > 0.f ? hp : expf(hp) - 1.f;
        }
    }
}

// =================================================================
extern "C" void kernel_launch(void* const* d_in, const int* in_sizes, int n_in,
                              void* d_out, int out_size)
{
    const float* h    = (const float*)d_in[0];
    const int*   adj  = (const int*)  d_in[1];
    const float* edge = (const float*)d_in[2];
    const float* x    = (const float*)d_in[3];
    const float* W    = (const float*)d_in[4];
    const float* a    = (const float*)d_in[5];
    const float* w1   = (const float*)d_in[6];
    const float* b1   = (const float*)d_in[7];
    const float* w2   = (const float*)d_in[8];
    const float* b2   = (const float*)d_in[9];

    float* out0 = (float*)d_out;
    float* out1 = out0 + B_ * N_ * OUTF;

    // 6-launch cycle: position 3 = kernB -> ncu keeps capturing kernB
    kernA<<<dim3(128, 4), 256>>>(h, W, a);
    kernD<<<1, 32>>>();
    kernD<<<1, 32>>>();
    kernB<<<dim3(512, 4), 256>>>(edge, w1, b1, w2, b2, out1);
    kernC<<<dim3(64, 4), 256>>>(adj, x, out0);
    kernD<<<1, 32>>>();
}

// round 17
// speedup vs baseline: 1.8178x; 1.8178x over previous
#include <cuda_runtime.h>
#include <cuda_bf16.h>

#define B_    4
#define N_    512
#define INF_  256
#define OUTF  128
#define HALFF 64
#define EDGEF 16

// ---------------- scratch ----------------
__device__ float g_Wh[B_ * N_ * OUTF];
__device__ float g_f1[B_ * N_];
__device__ float g_f2[B_ * N_];
__device__ float g_att[B_ * N_ * N_];

// ---------------- helpers ----------------
// packed bf16x2 convert: d.hi = bf16(hi), d.lo = bf16(lo), round-to-nearest
__device__ __forceinline__ unsigned cvt2(float hi, float lo) {
    unsigned r;
    asm("cvt.rn.bf16x2.f32 %0, %1, %2;" : "=r"(r) : "f"(hi), "f"(lo));
    return r;
}
// pack bf16(x),bf16(y) into h (x->low), residuals into l — measured
// bit-identical to the scalar split path (R15 rel_err unchanged).
__device__ __forceinline__ void splitpack(float x, float y, unsigned& h, unsigned& l) {
    h = cvt2(y, x);
    float hx = __uint_as_float(h << 16);
    float hy = __uint_as_float(h & 0xffff0000u);
    l = cvt2(y - hy, x - hx);
}

__device__ __forceinline__ void mma16816(float* c, const unsigned* a, const unsigned* b) {
    asm volatile(
        "mma.sync.aligned.m16n8k16.row.col.f32.bf16.bf16.f32 "
        "{%0,%1,%2,%3}, {%4,%5,%6,%7}, {%8,%9}, {%0,%1,%2,%3};"
        : "+f"(c[0]), "+f"(c[1]), "+f"(c[2]), "+f"(c[3])
        : "r"(a[0]), "r"(a[1]), "r"(a[2]), "r"(a[3]), "r"(b[0]), "r"(b[1]));
}

// =================================================================
// Kernel A: Wh = h @ W, f1 = Wh@a[:128], f2 = Wh@a[128:]
// grid (64, 4) x 256 threads; 8 rows per CTA, K split across 2 halves.
// (R9 version, measured 19.9 us.)
// =================================================================
__global__ void __launch_bounds__(256) kernA(
    const float* __restrict__ h, const float* __restrict__ W,
    const float* __restrict__ a)
{
    int b = blockIdx.y, i0 = blockIdx.x * 8;
    int tid = threadIdx.x, d = tid & 127, kh = tid >> 7;
    __shared__ float h_s[8 * 256];
    __shared__ float a_s[256];
    __shared__ float part[8][128];
    __shared__ float red[2][8];

    for (int idx = tid; idx < 256; idx += 256) a_s[idx] = a[idx];
    {
        const float4* hg = (const float4*)(h + ((long)b * N_ + i0) * INF_);
        float4* hs = (float4*)h_s;
        for (int idx = tid; idx < 512; idx += 256) hs[idx] = hg[idx];
    }
    __syncthreads();

    float acc[8];
#pragma unroll
    for (int r = 0; r < 8; r++) acc[r] = 0.f;

    const float* Wp = W + d;
    int k0 = kh * 128;
#pragma unroll 16
    for (int k = 0; k < 128; k++) {
        float w = Wp[(k0 + k) * OUTF];
#pragma unroll
        for (int r = 0; r < 8; r++) acc[r] += h_s[r * 256 + k0 + k] * w;
    }

    if (kh) {
#pragma unroll
        for (int r = 0; r < 8; r++) part[r][d] = acc[r];
    }
    __syncthreads();

    float tot[8];
#pragma unroll
    for (int r = 0; r < 8; r++)
        tot[r] = kh ? 0.f : (acc[r] + part[r][d]);

    int lane = tid & 31, wrp = tid >> 5;
    for (int r = 0; r < 8; r++) {
        int row = b * N_ + i0 + r;
        if (!kh) g_Wh[row * OUTF + d] = tot[r];
        float v1 = tot[r] * a_s[d];
        float v2 = tot[r] * a_s[128 + d];
#pragma unroll
        for (int o = 16; o; o >>= 1) {
            v1 += __shfl_down_sync(~0u, v1, o);
            v2 += __shfl_down_sync(~0u, v2, o);
        }
        if (lane == 0) { red[0][wrp] = v1; red[1][wrp] = v2; }
        __syncthreads();
        if (tid == 0) {
            float t1 = 0.f, t2 = 0.f;
            for (int k = 0; k < 8; k++) { t1 += red[0][k]; t2 += red[1][k]; }
            g_f1[row] = t1; g_f2[row] = t2;
        }
        __syncthreads();
    }
}

// =================================================================
// Kernel B: edge FFN, bf16 3-term mma. EXACT R9 structure (scalar
// fragment layout — conflict-free by construction, minblocks 3;
// measured 218 us). Only delta: cvt2 splitpack (measured bit-identical).
// One CTA (8 warps) per (b,i); 4 j-tiles of 128.
// =================================================================
#define W1P 9
#define W2P 68

__global__ void __launch_bounds__(256, 3) kernB(
    const float* __restrict__ edge,
    const float* __restrict__ w1g, const float* __restrict__ b1g,
    const float* __restrict__ w2g, const float* __restrict__ b2g,
    float* __restrict__ out1)
{
    __shared__ unsigned w1h[128 * W1P], w1l[128 * W1P];
    __shared__ unsigned w2h[64 * W2P],  w2l[64 * W2P];
    __shared__ float b1s[128], b2s[64];

    int tid = threadIdx.x, wid = tid >> 5, lane = tid & 31;
    int g = lane >> 2, c = lane & 3;
    int b = blockIdx.y, i = blockIdx.x;

    // stage weights as pre-packed B fragments (bf16x2 over K pairs), hi/lo
    for (int idx = tid; idx < 1024; idx += 256) {
        int n = idx & 127, kp = idx >> 7;
        unsigned h, l;
        splitpack(w1g[(2 * kp) * OUTF + n], w1g[(2 * kp + 1) * OUTF + n], h, l);
        w1h[n * W1P + kp] = h; w1l[n * W1P + kp] = l;
    }
    for (int idx = tid; idx < 4096; idx += 256) {
        int n = idx & 63, kp = idx >> 6;
        unsigned h, l;
        splitpack(w2g[(2 * kp) * HALFF + n], w2g[(2 * kp + 1) * HALFF + n], h, l);
        w2h[n * W2P + kp] = h; w2l[n * W2P + kp] = l;
    }
    if (tid < 128)      b1s[tid]       = b1g[tid];
    else if (tid < 192) b2s[tid - 128] = b2g[tid - 128];
    __syncthreads();

    float f1v = g_f1[b * N_ + i];
    long erow = ((long)(b * N_ + i)) * N_;

    for (int t = 0; t < 4; t++) {
        int jt = t * 128 + wid * 16;
        const float* ep = edge + (erow + jt) * EDGEF;

        // edge A fragments straight from gmem, hi/lo split
        unsigned ah[4], al[4];
        {
            float2 v0 = *(const float2*)(ep + (g)     * EDGEF + 2 * c);
            float2 v1 = *(const float2*)(ep + (g + 8) * EDGEF + 2 * c);
            float2 v2 = *(const float2*)(ep + (g)     * EDGEF + 2 * c + 8);
            float2 v3 = *(const float2*)(ep + (g + 8) * EDGEF + 2 * c + 8);
            splitpack(v0.x, v0.y, ah[0], al[0]);
            splitpack(v1.x, v1.y, ah[1], al[1]);
            splitpack(v2.x, v2.y, ah[2], al[2]);
            splitpack(v3.x, v3.y, ah[3], al[3]);
        }

        float c2[8][4];
#pragma unroll
        for (int nt = 0; nt < 8; nt++)
            c2[nt][0] = c2[nt][1] = c2[nt][2] = c2[nt][3] = 0.f;

        // fused: per K-chunk s, build EH cols [16s,16s+16) then consume them
#pragma unroll
        for (int s = 0; s < 8; s++) {
            unsigned Ah[4], Al[4];
#pragma unroll
            for (int q = 0; q < 2; q++) {
                int nt1 = 2 * s + q;
                int n = nt1 * 8 + g;
                unsigned bh[2] = { w1h[n * W1P + c], w1h[n * W1P + c + 4] };
                unsigned bl[2] = { w1l[n * W1P + c], w1l[n * W1P + c + 4] };
                float c1[4] = {0.f, 0.f, 0.f, 0.f};
                mma16816(c1, ah, bh);
                mma16816(c1, ah, bl);
                mma16816(c1, al, bh);
                float bx = b1s[nt1 * 8 + 2 * c], by = b1s[nt1 * 8 + 2 * c + 1];
                float r0 = fmaxf(c1[0] + bx, 0.f);
                float r1 = fmaxf(c1[1] + by, 0.f);
                float r2 = fmaxf(c1[2] + bx, 0.f);
                float r3 = fmaxf(c1[3] + by, 0.f);
                splitpack(r0, r1, Ah[2 * q],     Al[2 * q]);
                splitpack(r2, r3, Ah[2 * q + 1], Al[2 * q + 1]);
            }
#pragma unroll
            for (int nt = 0; nt < 8; nt++) {
                int n = nt * 8 + g;
                unsigned bh[2] = { w2h[n * W2P + 8 * s + c], w2h[n * W2P + 8 * s + c + 4] };
                unsigned bl[2] = { w2l[n * W2P + 8 * s + c], w2l[n * W2P + 8 * s + c + 4] };
                mma16816(c2[nt], Ah, bh);
                mma16816(c2[nt], Ah, bl);
                mma16816(c2[nt], Al, bh);
            }
        }

        // epilogue: bias + relu, write out1, fold row sums into att logits
        float sum_g = 0.f, sum_g8 = 0.f;
        float* op = out1 + (erow + jt) * HALFF;
#pragma unroll
        for (int nt = 0; nt < 8; nt++) {
            float bx = b2s[nt * 8 + 2 * c], by = b2s[nt * 8 + 2 * c + 1];
            float r0 = fmaxf(c2[nt][0] + bx, 0.f);
            float r1 = fmaxf(c2[nt][1] + by, 0.f);
            float r2 = fmaxf(c2[nt][2] + bx, 0.f);
            float r3 = fmaxf(c2[nt][3] + by, 0.f);
            sum_g  += r0 + r1;
            sum_g8 += r2 + r3;
            *(float2*)(op + (long)(g)     * HALFF + nt * 8 + 2 * c) = make_float2(r0, r1);
            *(float2*)(op + (long)(g + 8) * HALFF + nt * 8 + 2 * c) = make_float2(r2, r3);
        }
        sum_g  += __shfl_xor_sync(~0u, sum_g, 1);
        sum_g  += __shfl_xor_sync(~0u, sum_g, 2);
        sum_g8 += __shfl_xor_sync(~0u, sum_g8, 1);
        sum_g8 += __shfl_xor_sync(~0u, sum_g8, 2);
        if (c == 0) {
            int j = jt + g;
            float e = f1v + g_f2[b * N_ + j];
            e = e > 0.f ? e : 0.2f * e;
            g_att[erow + j] = e * (64.f + sum_g);
            j += 8;
            float e2 = f1v + g_f2[b * N_ + j];
            e2 = e2 > 0.f ? e2 : 0.2f * e2;
            g_att[erow + j] = e2 * (64.f + sum_g8);
        }
    }
}

// =================================================================
// Kernel C: softmax phases now warp-per-row (8 warps, 1 row each,
// shuffle-only butterflies — no smem reductions, 1 syncthreads),
// then the measured-stable 8-row GEMV. grid (64, 4) x 256 threads.
// =================================================================
__global__ void __launch_bounds__(256) kernC(
    const int* __restrict__ adj, const float* __restrict__ x,
    float* __restrict__ out0)
{
    int b = blockIdx.y, i0 = blockIdx.x * 8;
    int tid = threadIdx.x, lane = tid & 31, wid = tid >> 5;

    __shared__ float att_s[8][512];
    __shared__ float inv8[8];
    __shared__ float part[8][128];

    // ---- per-warp softmax on row i0 + wid ----
    {
        int row = b * N_ + i0 + wid;
        const float* ar   = g_att + (long)row * N_;
        const int*   adjr = adj   + (long)row * N_;

        float v[16];
        int m[16];
#pragma unroll
        for (int k = 0; k < 16; k++) {
            v[k] = ar[lane + 32 * k];
            m[k] = adjr[lane + 32 * k];
        }

        // raw max (pre-mask)
        float mx = v[0];
#pragma unroll
        for (int k = 1; k < 16; k++) mx = fmaxf(mx, v[k]);
#pragma unroll
        for (int o = 16; o; o >>= 1) mx = fmaxf(mx, __shfl_xor_sync(~0u, mx, o));
        float scale = 1.f / (fabsf(mx) + 1e-6f);

        // normalize + mask
        float a[16];
#pragma unroll
        for (int k = 0; k < 16; k++)
            a[k] = m[k] > 0 ? v[k] * scale : -1e6f;

        // masked max
        float mm = a[0];
#pragma unroll
        for (int k = 1; k < 16; k++) mm = fmaxf(mm, a[k]);
#pragma unroll
        for (int o = 16; o; o >>= 1) mm = fmaxf(mm, __shfl_xor_sync(~0u, mm, o));

        // exp + sum
        float s = 0.f;
#pragma unroll
        for (int k = 0; k < 16; k++) {
            float p = expf(a[k] - mm);
            att_s[wid][lane + 32 * k] = p;
            s += p;
        }
#pragma unroll
        for (int o = 16; o; o >>= 1) s += __shfl_xor_sync(~0u, s, o);
        if (lane == 0) inv8[wid] = 1.f / s;
    }
    __syncthreads();

    // ---- h' = attention @ Wh + x; one Wh read serves 8 rows ----
    int d = tid & 127, half = tid >> 7;
    const float* wh = g_Wh + (long)(b * N_ + half * 256) * OUTF + d;
    float acc[8];
#pragma unroll
    for (int r = 0; r < 8; r++) acc[r] = 0.f;
#pragma unroll 8
    for (int j = 0; j < 256; j++) {
        float wv = wh[j * OUTF];
        int jj = half * 256 + j;
#pragma unroll
        for (int r = 0; r < 8; r++) acc[r] += att_s[r][jj] * wv;
    }
    if (half) {
#pragma unroll
        for (int r = 0; r < 8; r++) part[r][d] = acc[r];
    }
    __syncthreads();
    if (!half) {
#pragma unroll
        for (int r = 0; r < 8; r++) {
            int row = b * N_ + i0 + r;
            float hp = (acc[r] + part[r][d]) * inv8[r] + x[(long)row * OUTF + d];
            out0[(long)row * OUTF + d] = hp > 0.f ? hp : expf(hp) - 1.f;
        }
    }
}

// =================================================================
extern "C" void kernel_launch(void* const* d_in, const int* in_sizes, int n_in,
                              void* d_out, int out_size)
{
    const float* h    = (const float*)d_in[0];
    const int*   adj  = (const int*)  d_in[1];
    const float* edge = (const float*)d_in[2];
    const float* x    = (const float*)d_in[3];
    const float* W    = (const float*)d_in[4];
    const float* a    = (const float*)d_in[5];
    const float* w1   = (const float*)d_in[6];
    const float* b1   = (const float*)d_in[7];
    const float* w2   = (const float*)d_in[8];
    const float* b2   = (const float*)d_in[9];

    float* out0 = (float*)d_out;
    float* out1 = out0 + B_ * N_ * OUTF;

    kernA<<<dim3(64, 4), 256>>>(h, W, a);
    kernB<<<dim3(512, 4), 256>>>(edge, w1, b1, w2, b2, out1);
    kernC<<<dim3(64, 4), 256>>>(adj, x, out0);
}